// round 15
// baseline (speedup 1.0000x reference)
#include <cuda_runtime.h>
#include <cuda_fp16.h>
#include <math.h>
#include <stdint.h>

// ---------------- problem constants ----------------
#define NB      8
#define HH      56
#define WW      56
#define LSEQ    3136
#define LHALF   1568
#define BLTOT   25088
#define CDIM    384
#define DINNER  768
#define DSTATE  64
#define NHM     12
#define DINPROJ 1676
#define CONVDIM 896
#define NHA     12
#define NWIN    512
#define MTILES  196   // BLTOT/128
#define NPAIR   96    // NB*NHM

// ---------------- fp32 scratch ----------------
__device__ float g_xs   [(size_t)BLTOT * DINNER];
__device__ float g_Bm   [(size_t)BLTOT * DSTATE];
__device__ float g_Cm   [(size_t)BLTOT * DSTATE];
__device__ float g_dt   [(size_t)BLTOT * NHM];
__device__ float g_dA   [(size_t)BLTOT * NHM];
__device__ float g_y    [(size_t)BLTOT * DINNER];
__device__ float g_gate [(size_t)BLTOT * NHA];
__device__ float g_x2   [(size_t)BLTOT * CDIM];
__device__ float g_biasF[CDIM];
__device__ float g_hmid [(size_t)NPAIR * 64 * 64];
__device__ float g_pw   [(size_t)NPAIR * LHALF];

// ---------------- fp16 activation scratch ----------------
__device__ __half b_zx  [(size_t)BLTOT * DINPROJ];
__device__ __half b_xn  [(size_t)BLTOT * CDIM];
__device__ __half b_g   [(size_t)BLTOT * DINNER];
__device__ __half b_ag  [(size_t)BLTOT * CDIM];
__device__ __half b_h1  [(size_t)BLTOT * 1536];
__device__ __half b_xn2 [(size_t)BLTOT * CDIM];
__device__ __half b_qkv [(size_t)BLTOT * 1152];

// ---------------- fp16 weights ----------------
__device__ __half w_in  [(size_t)DINPROJ * CDIM];
__device__ __half w_qkv [(size_t)1152 * CDIM];
__device__ __half w_fc1 [(size_t)1536 * CDIM];
__device__ __half w_fc2 [(size_t)CDIM * 1536];
__device__ __half w_fusA[(size_t)CDIM * CDIM];
__device__ __half w_fusB[(size_t)CDIM * CDIM];
__device__ __half w_outD[(size_t)DINNER * CDIM];
__device__ __half w_prjD[(size_t)CDIM * CDIM];
__device__ __half w_outF[(size_t)CDIM * DINNER];
__device__ __half w_prjF[(size_t)CDIM * CDIM];

__device__ __forceinline__ uint32_t smem_u32(const void* p) {
    uint32_t a;
    asm("{ .reg .u64 t; cvta.to.shared.u64 t, %1; cvt.u32.u64 %0, t; }" : "=r"(a) : "l"(p));
    return a;
}

// ================= mma.sync fp16 GEMM (round-9 config: 128x128, 2 CTA/SM) =================
#define BKG   64
#define ASTR  72
#define MATSZ (128 * ASTR)
#define STAGESZ (2 * MATSZ)
#define GEMM_SMEM (2 * STAGESZ * 2)

__device__ __forceinline__ void ldsm4(uint32_t& r0, uint32_t& r1, uint32_t& r2, uint32_t& r3, uint32_t a) {
    asm volatile("ldmatrix.sync.aligned.m8n8.x4.shared.b16 {%0,%1,%2,%3}, [%4];"
                 : "=r"(r0), "=r"(r1), "=r"(r2), "=r"(r3) : "r"(a));
}
__device__ __forceinline__ void mma16816(float* c, const uint32_t* a, const uint32_t* b) {
    asm volatile("mma.sync.aligned.m16n8k16.row.col.f32.f16.f16.f32 "
                 "{%0,%1,%2,%3}, {%4,%5,%6,%7}, {%8,%9}, {%0,%1,%2,%3};"
                 : "+f"(c[0]), "+f"(c[1]), "+f"(c[2]), "+f"(c[3])
                 : "r"(a[0]), "r"(a[1]), "r"(a[2]), "r"(a[3]), "r"(b[0]), "r"(b[1]));
}
__device__ __forceinline__ void cpasync16(uint32_t dst, const void* src, uint32_t sz) {
    asm volatile("cp.async.cg.shared.global [%0], [%1], 16, %2;"
                 :: "r"(dst), "l"(src), "r"(sz) : "memory");
}

__global__ void __launch_bounds__(256, 2)
mma_gemm(const __half* __restrict__ Aw, const __half* __restrict__ Bw,
         const float* __restrict__ bias, const float* __restrict__ res,
         float* __restrict__ Cf, __half* __restrict__ Chalf,
         int ldh, int M, int N, int K, int act)
{
    extern __shared__ __align__(16) __half smem[];
    const int tid = threadIdx.x;
    const int wid = tid >> 5, lane = tid & 31;
    const int warp_m = wid & 1, warp_n = wid >> 1;
    const int m0 = blockIdx.y * 128, n0 = blockIdx.x * 128;

    const int lrow = tid >> 1, lseg = tid & 1;
    const bool bvalid = (n0 + lrow) < N;
    const uint32_t sbase = smem_u32(smem);

    float acc[4][4][4];
#pragma unroll
    for (int i = 0; i < 4; i++)
#pragma unroll
        for (int j = 0; j < 4; j++)
#pragma unroll
            for (int e = 0; e < 4; e++) acc[i][j][e] = 0.f;

    const int nch = K / BKG;

    auto load_stage = [&](int ch, int st) {
        const int k0 = ch * BKG;
        uint32_t so = (uint32_t)(st * STAGESZ + lrow * ASTR + lseg * 32) * 2;
        const __half* ga = Aw + (size_t)(m0 + lrow) * K + k0 + lseg * 32;
        const __half* gb = Bw + (size_t)(n0 + lrow) * K + k0 + lseg * 32;
        uint32_t bs = bvalid ? 16u : 0u;
#pragma unroll
        for (int u = 0; u < 4; u++) {
            cpasync16(sbase + so + u * 16,             ga + u * 8, 16u);
            cpasync16(sbase + so + MATSZ * 2 + u * 16, gb + u * 8, bs);
        }
    };

    load_stage(0, 0);
    asm volatile("cp.async.commit_group;" ::: "memory");

    for (int ch = 0; ch < nch; ch++) {
        const int st = ch & 1;
        if (ch + 1 < nch) load_stage(ch + 1, st ^ 1);
        asm volatile("cp.async.commit_group;" ::: "memory");
        asm volatile("cp.async.wait_group 1;" ::: "memory");
        __syncthreads();

        const uint32_t sA = sbase + (uint32_t)(st * STAGESZ) * 2;
        const uint32_t sB = sA + MATSZ * 2;
        const int lr = lane & 15;
        const int lk = (lane >> 4) << 3;

#pragma unroll
        for (int ks = 0; ks < BKG; ks += 16) {
            uint32_t bh[4][2];
#pragma unroll
            for (int np = 0; np < 2; np++) {
                uint32_t off = (uint32_t)((warp_n * 32 + np * 16 + lr) * ASTR + ks + lk) * 2;
                uint32_t r0, r1, r2, r3;
                ldsm4(r0, r1, r2, r3, sB + off);
                bh[np*2+0][0] = r0; bh[np*2+0][1] = r2;
                bh[np*2+1][0] = r1; bh[np*2+1][1] = r3;
            }
#pragma unroll
            for (int mt = 0; mt < 4; mt++) {
                uint32_t off = (uint32_t)((warp_m * 64 + mt * 16 + lr) * ASTR + ks + lk) * 2;
                uint32_t a[4];
                ldsm4(a[0], a[1], a[2], a[3], sA + off);
#pragma unroll
                for (int nt = 0; nt < 4; nt++) mma16816(acc[mt][nt], a, bh[nt]);
            }
        }
        __syncthreads();
    }

    const int mrow = m0 + warp_m * 64 + (lane >> 2);
    const int ncol = n0 + warp_n * 32 + (lane & 3) * 2;
#pragma unroll
    for (int mt = 0; mt < 4; mt++) {
#pragma unroll
        for (int nt = 0; nt < 4; nt++) {
#pragma unroll
            for (int e = 0; e < 4; e++) {
                int r = mrow + mt * 16 + ((e >> 1) ? 8 : 0);
                int c = ncol + nt * 8 + (e & 1);
                if (c < N) {
                    float v = acc[mt][nt][e];
                    if (bias) v += bias[c];
                    if (act)  v = 0.5f * v * (1.f + erff(v * 0.70710678118654752f));
                    if (res)  v += res[(size_t)r * N + c];
                    if (Cf)    Cf[(size_t)r * N + c] = v;
                    if (Chalf) Chalf[(size_t)r * ldh + c] = __float2half_rn(v);
                }
            }
        }
    }
}

// ---------------- batched weight transpose/copy + fp16 (8 jobs) ----------------
struct WJob { const float* src; __half* dst; int K; int N; long off; };
__global__ void wconv_all_kernel(WJob j0, WJob j1, WJob j2, WJob j3, WJob j4, WJob j5,
                                 WJob j6, WJob j7, long total)
{
    long idx = (long)blockIdx.x * blockDim.x + threadIdx.x;
    if (idx >= total) return;
    WJob j;
    if      (idx < j1.off) j = j0;
    else if (idx < j2.off) j = j1;
    else if (idx < j3.off) j = j2;
    else if (idx < j4.off) j = j3;
    else if (idx < j5.off) j = j4;
    else if (idx < j6.off) j = j5;
    else if (idx < j7.off) j = j6;
    else                   j = j7;
    long li = idx - j.off;
    int k = (int)(li % j.K);
    long n = li / j.K;
    j.dst[li] = __float2half_rn(j.src[(size_t)k * j.N + n]);
}

// ---------------- combined bias ----------------
__global__ void biasf_kernel(const float* __restrict__ fusion_b, const float* __restrict__ proj_b,
                             const float* __restrict__ fusion_w, float* __restrict__ outb)
{
    int n = blockIdx.x * blockDim.x + threadIdx.x;
    if (n >= CDIM) return;
    float a = fusion_b[n];
    for (int j = 0; j < CDIM; j++)
        a += proj_b[j] * fusion_w[(size_t)(CDIM + j) * CDIM + n];
    outb[n] = a;
}

// ---------------- LayerNorm (384) -> fp16, warp per row ----------------
__global__ void ln_kernel(const float* __restrict__ x, const float* __restrict__ w,
                          const float* __restrict__ b, __half* __restrict__ oh)
{
    int row  = blockIdx.x * 8 + (threadIdx.x >> 5);
    int lane = threadIdx.x & 31;
    if (row >= BLTOT) return;
    const float* xr = x + (size_t)row * CDIM;
    float v[12];
    float s = 0.f;
#pragma unroll
    for (int i = 0; i < 3; i++) {
        float4 t = *(const float4*)(xr + i * 128 + lane * 4);
        v[i*4+0]=t.x; v[i*4+1]=t.y; v[i*4+2]=t.z; v[i*4+3]=t.w;
        s += t.x + t.y + t.z + t.w;
    }
#pragma unroll
    for (int o = 16; o; o >>= 1) s += __shfl_xor_sync(0xffffffffu, s, o);
    float mu = s * (1.f / CDIM);
    float ss = 0.f;
#pragma unroll
    for (int i = 0; i < 12; i++) { float d = v[i] - mu; ss += d * d; }
#pragma unroll
    for (int o = 16; o; o >>= 1) ss += __shfl_xor_sync(0xffffffffu, ss, o);
    float rstd = rsqrtf(ss * (1.f / CDIM) + 1e-5f);
#pragma unroll
    for (int i = 0; i < 3; i++) {
        int c = i * 128 + lane * 4;
        float4 wv = *(const float4*)(w + c);
        float4 bv = *(const float4*)(b + c);
        size_t o0 = (size_t)row * CDIM + c;
        oh[o0+0] = __float2half_rn((v[i*4+0]-mu)*rstd*wv.x + bv.x);
        oh[o0+1] = __float2half_rn((v[i*4+1]-mu)*rstd*wv.y + bv.y);
        oh[o0+2] = __float2half_rn((v[i*4+2]-mu)*rstd*wv.z + bv.z);
        oh[o0+3] = __float2half_rn((v[i*4+3]-mu)*rstd*wv.w + bv.w);
    }
}

// ---------------- depthwise causal conv(k=4) + SiLU, split (fp16 zx in) ----------------
__global__ void conv_kernel(const __half* __restrict__ zx, const float* __restrict__ cw,
                            const float* __restrict__ cb,
                            float* __restrict__ xs, float* __restrict__ Bout,
                            float* __restrict__ Cout)
{
    long idx = (long)blockIdx.x * blockDim.x + threadIdx.x;
    if (idx >= (long)BLTOT * CONVDIM) return;
    int c  = (int)(idx % CONVDIM);
    long bl = idx / CONVDIM;
    int l  = (int)(bl % LSEQ);
    float acc = cb[c];
    const float w0 = cw[c*4+0], w1 = cw[c*4+1], w2 = cw[c*4+2], w3 = cw[c*4+3];
    const __half* base = zx + (size_t)bl * DINPROJ + DINNER + c;
    if (l >= 3) acc += w0 * __half2float(base[-(size_t)3 * DINPROJ]);
    if (l >= 2) acc += w1 * __half2float(base[-(size_t)2 * DINPROJ]);
    if (l >= 1) acc += w2 * __half2float(base[-(size_t)1 * DINPROJ]);
    acc += w3 * __half2float(base[0]);
    acc = acc / (1.f + expf(-acc));
    if (c < DINNER)            xs[(size_t)bl * DINNER + c] = acc;
    else if (c < DINNER + 64)  Bout[(size_t)bl * 64 + (c - DINNER)] = acc;
    else                       Cout[(size_t)bl * 64 + (c - DINNER - 64)] = acc;
}

// ---------------- dt / dA (fp16 zx in) ----------------
__global__ void dt_kernel(const __half* __restrict__ zx, const float* __restrict__ dtb,
                          const float* __restrict__ Alog,
                          float* __restrict__ dt, float* __restrict__ dA)
{
    long idx = (long)blockIdx.x * blockDim.x + threadIdx.x;
    if (idx >= (long)BLTOT * NHM) return;
    int h = (int)(idx % NHM);
    long bl = idx / NHM;
    float x = __half2float(zx[(size_t)bl * DINPROJ + (DINPROJ - NHM) + h]) + dtb[h];
    float sp = (x > 20.f) ? x : log1pf(expf(x));
    float A  = -expf(Alog[h]);
    dt[idx] = sp;
    dA[idx] = expf(sp * A);
}

// ---------------- selective scan, L split in 2 halves per (b,h) ----------------
// half 0: exact scan of [0,1568), stores final state h_mid.
// half 1: local scan of [1568,3136) with h0=0, stores running prod(dA) per t.
__global__ void __launch_bounds__(512, 1)
scan1_kernel(const float* __restrict__ xs, const float* __restrict__ Bm,
             const float* __restrict__ Cm, const float* __restrict__ dt,
             const float* __restrict__ dA, const float* __restrict__ Dp,
             float* __restrict__ y, float* __restrict__ hmid, float* __restrict__ pw)
{
    const int T = 16;
    int pair = blockIdx.x >> 1;
    int half = blockIdx.x & 1;
    int b = pair / NHM;
    int h = pair % NHM;
    int tid = threadIdx.x;
    int p  = tid >> 3;
    int nc = tid & 7;
    int n0 = nc * 8;
    __shared__ float sB[T][64], sC[T][64], sX[T][64], sDt[T], sDa[T];
    float s[8];
#pragma unroll
    for (int j = 0; j < 8; j++) s[j] = 0.f;
    float w = 1.f;
    float Dh = Dp[h];
    size_t base = (size_t)b * LSEQ;
    const int lbeg = half * LHALF, lend = lbeg + LHALF;

    for (int l0 = lbeg; l0 < lend; l0 += T) {
        __syncthreads();
        for (int idx = tid; idx < T * 64; idx += 512) {
            int t = idx >> 6, j = idx & 63;
            size_t r = base + l0 + t;
            sB[t][j] = Bm[r * 64 + j];
            sC[t][j] = Cm[r * 64 + j];
            sX[t][j] = xs[r * DINNER + h * 64 + j];
        }
        if (tid < T) {
            size_t r = base + l0 + tid;
            sDt[tid] = dt[r * NHM + h];
            sDa[tid] = dA[r * NHM + h];
        }
        __syncthreads();
#pragma unroll 4
        for (int t = 0; t < T; t++) {
            float da  = sDa[t];
            float dtx = sDt[t] * sX[t][p];
            float part = 0.f;
#pragma unroll
            for (int j = 0; j < 8; j++) {
                s[j] = s[j] * da + dtx * sB[t][n0 + j];
                part += s[j] * sC[t][n0 + j];
            }
            part += __shfl_xor_sync(0xffffffffu, part, 1);
            part += __shfl_xor_sync(0xffffffffu, part, 2);
            part += __shfl_xor_sync(0xffffffffu, part, 4);
            if (half) {
                w *= da;
                if (tid == 0) pw[(size_t)pair * LHALF + (l0 - LHALF) + t] = w;
            }
            if (nc == 0)
                y[(base + l0 + t) * DINNER + h * 64 + p] = part + Dh * sX[t][p];
        }
    }
    if (half == 0) {
#pragma unroll
        for (int j = 0; j < 8; j++)
            hmid[((size_t)pair * 64 + p) * 64 + n0 + j] = s[j];
    }
}

// ---------------- fixup: y[t] += pw[t] * (C_t . h_mid), second half only ----------------
__global__ void __launch_bounds__(512, 2)
fixup_kernel(const float* __restrict__ Cm, const float* __restrict__ hmid,
             const float* __restrict__ pw, float* __restrict__ y)
{
    int pair = blockIdx.y;
    int tch  = blockIdx.x;          // 0..7, 196 t each
    int b = pair / NHM, h = pair % NHM;
    int tid = threadIdx.x;
    int p  = tid >> 3;
    int nc = tid & 7;
    int n0 = nc * 8;
    float hm[8];
#pragma unroll
    for (int j = 0; j < 8; j++)
        hm[j] = hmid[((size_t)pair * 64 + p) * 64 + n0 + j];
    size_t base = (size_t)b * LSEQ + LHALF;
    int t0 = tch * 196, t1 = t0 + 196;
    for (int t = t0; t < t1; t++) {
        const float* Cr = Cm + (base + t) * 64;
        float part = 0.f;
#pragma unroll
        for (int j = 0; j < 8; j++) part += hm[j] * __ldg(Cr + n0 + j);
        part += __shfl_xor_sync(0xffffffffu, part, 1);
        part += __shfl_xor_sync(0xffffffffu, part, 2);
        part += __shfl_xor_sync(0xffffffffu, part, 4);
        if (nc == 0) {
            float wv = pw[(size_t)pair * LHALF + t];
            y[(base + t) * DINNER + h * 64 + p] += wv * part;
        }
    }
}

// ---------------- gated rmsnorm (768) -> fp16 (fp16 z in) ----------------
__global__ void rmsgate_kernel(const float* __restrict__ y, const __half* __restrict__ zx,
                               const float* __restrict__ mw, __half* __restrict__ oh)
{
    int row  = blockIdx.x * 8 + (threadIdx.x >> 5);
    int lane = threadIdx.x & 31;
    if (row >= BLTOT) return;
    const float* yr = y  + (size_t)row * DINNER;
    const __half* zr = zx + (size_t)row * DINPROJ;
    float g[24];
    float ss = 0.f;
#pragma unroll
    for (int i = 0; i < 6; i++) {
        int c = i * 128 + lane * 4;
        float4 yv = *(const float4*)(yr + c);
        __half2 zp0 = *(const __half2*)(zr + c);
        __half2 zp1 = *(const __half2*)(zr + c + 2);
        float zf0 = __half2float(zp0.x), zf1 = __half2float(zp0.y);
        float zf2 = __half2float(zp1.x), zf3 = __half2float(zp1.y);
        float z0 = zf0 / (1.f + expf(-zf0));
        float z1 = zf1 / (1.f + expf(-zf1));
        float z2 = zf2 / (1.f + expf(-zf2));
        float z3 = zf3 / (1.f + expf(-zf3));
        g[i*4+0] = yv.x * z0; g[i*4+1] = yv.y * z1;
        g[i*4+2] = yv.z * z2; g[i*4+3] = yv.w * z3;
        ss += g[i*4+0]*g[i*4+0] + g[i*4+1]*g[i*4+1] + g[i*4+2]*g[i*4+2] + g[i*4+3]*g[i*4+3];
    }
#pragma unroll
    for (int o = 16; o; o >>= 1) ss += __shfl_xor_sync(0xffffffffu, ss, o);
    float rstd = rsqrtf(ss * (1.f / DINNER) + 1e-5f);
#pragma unroll
    for (int i = 0; i < 6; i++) {
        int c = i * 128 + lane * 4;
        float4 wv = *(const float4*)(mw + c);
        size_t o0 = (size_t)row * DINNER + c;
        oh[o0+0] = __float2half_rn(g[i*4+0]*rstd*wv.x);
        oh[o0+1] = __float2half_rn(g[i*4+1]*rstd*wv.y);
        oh[o0+2] = __float2half_rn(g[i*4+2]*rstd*wv.z);
        oh[o0+3] = __float2half_rn(g[i*4+3]*rstd*wv.w);
    }
}

// ---------------- attention gate ----------------
__global__ void gate_kernel(const __half* __restrict__ xn, const float* __restrict__ gw,
                            const float* __restrict__ gb, float* __restrict__ out)
{
    int row  = blockIdx.x * 8 + (threadIdx.x >> 5);
    int lane = threadIdx.x & 31;
    if (row >= BLTOT) return;
    const __half* xr = xn + (size_t)row * CDIM;
    float acc[12];
#pragma unroll
    for (int h = 0; h < 12; h++) acc[h] = 0.f;
    for (int c = lane; c < CDIM; c += 32) {
        float xv = __half2float(xr[c]);
        const float* g = gw + c * 12;
#pragma unroll
        for (int h = 0; h < 12; h++) acc[h] += xv * g[h];
    }
#pragma unroll
    for (int h = 0; h < 12; h++)
#pragma unroll
        for (int o = 16; o; o >>= 1) acc[h] += __shfl_xor_sync(0xffffffffu, acc[h], o);
    if (lane == 0) {
#pragma unroll
        for (int h = 0; h < 12; h++) {
            float a = acc[h] + gb[h];
            out[(size_t)row * NHA + h] = 1.f / (1.f + expf(-a));
        }
    }
}

// ---------------- window attention (fp16 qkv) -> gated fp16 output ----------------
__global__ void __launch_bounds__(64)
attn_kernel(const __half* __restrict__ qkv, const float* __restrict__ gate,
            __half* __restrict__ oh)
{
    int wid = blockIdx.x;
    int h   = blockIdx.y;
    int b   = wid >> 6;
    int rem = wid & 63;
    int wh  = rem >> 3;
    int ww  = rem & 7;
    __shared__ float q[49][33], k[49][33], v[49][33];
    int tid = threadIdx.x;
    for (int idx = tid; idx < 49 * 32; idx += 64) {
        int i = idx >> 5, d = idx & 31;
        int r = i / 7, c = i % 7;
        int l = (wh * 7 + r) * WW + ww * 7 + c;
        size_t rowoff = ((size_t)b * LSEQ + l) * 1152 + h * 32 + d;
        q[i][d] = __half2float(qkv[rowoff]) * 0.17677669529663687f;
        k[i][d] = __half2float(qkv[rowoff + 384]);
        v[i][d] = __half2float(qkv[rowoff + 768]);
    }
    __syncthreads();
    if (tid < 49) {
        int i = tid;
        int r = i / 7, c = i % 7;
        int l = (wh * 7 + r) * WW + ww * 7 + c;
        float sc[49];
        float mx = -1e30f;
        for (int j = 0; j < 49; j++) {
            float a = 0.f;
#pragma unroll
            for (int d = 0; d < 32; d++) a += q[i][d] * k[j][d];
            sc[j] = a;
            mx = fmaxf(mx, a);
        }
        float sum = 0.f;
        for (int j = 0; j < 49; j++) { sc[j] = expf(sc[j] - mx); sum += sc[j]; }
        float ga = gate[((size_t)b * LSEQ + l) * NHA + h];
        float inv = ga / sum;
        size_t o0 = ((size_t)b * LSEQ + l) * CDIM + h * 32;
#pragma unroll
        for (int d = 0; d < 32; d++) {
            float o = 0.f;
            for (int j = 0; j < 49; j++) o += sc[j] * v[j][d];
            oh[o0 + d] = __float2half_rn(o * inv);
        }
    }
}

// ---------------- launch ----------------
static void* devptr(const void* sym) {
    void* p = nullptr;
    cudaGetSymbolAddress(&p, sym);
    return p;
}

extern "C" void kernel_launch(void* const* d_in, const int* in_sizes, int n_in,
                              void* d_out, int out_size)
{
    const float* x       = (const float*)d_in[0];
    const float* norm1_w = (const float*)d_in[1];
    const float* norm1_b = (const float*)d_in[2];
    const float* W_in    = (const float*)d_in[3];
    const float* conv_w  = (const float*)d_in[4];
    const float* conv_b  = (const float*)d_in[5];
    const float* dt_bias = (const float*)d_in[6];
    const float* A_log   = (const float*)d_in[7];
    const float* Dp      = (const float*)d_in[8];
    const float* mnorm_w = (const float*)d_in[9];
    const float* W_out   = (const float*)d_in[10];
    const float* qkv_w   = (const float*)d_in[11];
    const float* qkv_b   = (const float*)d_in[12];
    const float* gate_w  = (const float*)d_in[13];
    const float* gate_b  = (const float*)d_in[14];
    const float* proj_w  = (const float*)d_in[15];
    const float* proj_b  = (const float*)d_in[16];
    const float* fusion_w= (const float*)d_in[17];
    const float* fusion_b= (const float*)d_in[18];
    const float* norm2_w = (const float*)d_in[19];
    const float* norm2_b = (const float*)d_in[20];
    const float* fc1_w   = (const float*)d_in[21];
    const float* fc1_b   = (const float*)d_in[22];
    const float* fc2_w   = (const float*)d_in[23];
    const float* fc2_b   = (const float*)d_in[24];
    float* out = (float*)d_out;

    cudaFuncSetAttribute(mma_gemm, cudaFuncAttributeMaxDynamicSharedMemorySize, GEMM_SMEM);

    float* p_xs  = (float*)devptr(g_xs);
    float* p_Bm  = (float*)devptr(g_Bm);
    float* p_Cm  = (float*)devptr(g_Cm);
    float* p_dt  = (float*)devptr(g_dt);
    float* p_dA  = (float*)devptr(g_dA);
    float* p_y   = (float*)devptr(g_y);
    float* p_gt  = (float*)devptr(g_gate);
    float* p_x2  = (float*)devptr(g_x2);
    float* p_bF  = (float*)devptr(g_biasF);
    float* p_hm  = (float*)devptr(g_hmid);
    float* p_pw  = (float*)devptr(g_pw);

    __half* zx_h  = (__half*)devptr(b_zx);
    __half* xn_h  = (__half*)devptr(b_xn);
    __half* gh    = (__half*)devptr(b_g);
    __half* ag_h  = (__half*)devptr(b_ag);
    __half* h1_h  = (__half*)devptr(b_h1);
    __half* xn2_h = (__half*)devptr(b_xn2);
    __half* qkv_h = (__half*)devptr(b_qkv);

    __half* pw_in   = (__half*)devptr(w_in);
    __half* pw_qkv  = (__half*)devptr(w_qkv);
    __half* pw_fc1  = (__half*)devptr(w_fc1);
    __half* pw_fc2  = (__half*)devptr(w_fc2);
    __half* pw_fusA = (__half*)devptr(w_fusA);
    __half* pw_fusB = (__half*)devptr(w_fusB);
    __half* pw_outD = (__half*)devptr(w_outD);
    __half* pw_prjD = (__half*)devptr(w_prjD);
    __half* pw_outF = (__half*)devptr(w_outF);
    __half* pw_prjF = (__half*)devptr(w_prjF);

    // 1) batched weight transpose/copy + fp16
    {
        WJob j0{W_in,                 pw_in,   CDIM,            DINPROJ, 0};
        WJob j1{qkv_w,                pw_qkv,  CDIM,            1152,    0};
        WJob j2{fc1_w,                pw_fc1,  CDIM,            1536,    0};
        WJob j3{fc2_w,                pw_fc2,  1536,            CDIM,    0};
        WJob j4{fusion_w,             pw_fusA, CDIM,            CDIM,    0};
        WJob j5{fusion_w + CDIM*CDIM, pw_fusB, CDIM,            CDIM,    0};
        WJob j6{W_out,                pw_outD, DINNER * CDIM,   1,       0};
        WJob j7{proj_w,               pw_prjD, CDIM * CDIM,     1,       0};
        long off = 0;
        j0.off = off; off += (long)j0.K * j0.N;
        j1.off = off; off += (long)j1.K * j1.N;
        j2.off = off; off += (long)j2.K * j2.N;
        j3.off = off; off += (long)j3.K * j3.N;
        j4.off = off; off += (long)j4.K * j4.N;
        j5.off = off; off += (long)j5.K * j5.N;
        j6.off = off; off += (long)j6.K * j6.N;
        j7.off = off; off += (long)j7.K * j7.N;
        wconv_all_kernel<<<(unsigned)((off + 255) / 256), 256>>>(j0, j1, j2, j3, j4, j5, j6, j7, off);
    }

    // 2) combined bias + weight folds
    biasf_kernel<<<2, 192>>>(fusion_b, proj_b, fusion_w, p_bF);
    mma_gemm<<<dim3(6, 3), 256, GEMM_SMEM>>>(pw_fusA, pw_outD,
        nullptr, nullptr, nullptr, pw_outF, DINNER, CDIM, DINNER, CDIM, 0);
    mma_gemm<<<dim3(3, 3), 256, GEMM_SMEM>>>(pw_fusB, pw_prjD,
        nullptr, nullptr, nullptr, pw_prjF, CDIM, CDIM, CDIM, CDIM, 0);

    // 3) norm1 -> fp16
    ln_kernel<<<BLTOT / 8, 256>>>(x, norm1_w, norm1_b, xn_h);

    // 4) attention gate
    gate_kernel<<<BLTOT / 8, 256>>>(xn_h, gate_w, gate_b, p_gt);

    // 5) qkv -> fp16
    mma_gemm<<<dim3(9, MTILES), 256, GEMM_SMEM>>>(xn_h, pw_qkv,
        qkv_b, nullptr, nullptr, qkv_h, 1152, BLTOT, 1152, CDIM, 0);

    // 6) window attention
    attn_kernel<<<dim3(NWIN, NHA), 64>>>(qkv_h, p_gt, ag_h);

    // 7) in_proj -> zx (fp16)
    mma_gemm<<<dim3(14, MTILES), 256, GEMM_SMEM>>>(xn_h, pw_in,
        nullptr, nullptr, nullptr, zx_h, DINPROJ, BLTOT, DINPROJ, CDIM, 0);

    // 8) conv + 9) dt
    {
        long tot = (long)BLTOT * CONVDIM;
        conv_kernel<<<(unsigned)((tot + 255) / 256), 256>>>(zx_h, conv_w, conv_b, p_xs, p_Bm, p_Cm);
        long tot2 = (long)BLTOT * NHM;
        dt_kernel<<<(unsigned)((tot2 + 255) / 256), 256>>>(zx_h, dt_bias, A_log, p_dt, p_dA);
    }

    // 10) split scan + 11) fixup
    scan1_kernel<<<NPAIR * 2, 512>>>(p_xs, p_Bm, p_Cm, p_dt, p_dA, Dp, p_y, p_hm, p_pw);
    fixup_kernel<<<dim3(8, NPAIR), 512>>>(p_Cm, p_hm, p_pw, p_y);

    // 12) gated rmsnorm -> g fp16
    rmsgate_kernel<<<BLTOT / 8, 256>>>(p_y, zx_h, mnorm_w, gh);

    // 13) x2 = x + g @ w_outF + biasF
    mma_gemm<<<dim3(3, MTILES), 256, GEMM_SMEM>>>(gh, pw_outF,
        p_bF, x, p_x2, nullptr, 0, BLTOT, CDIM, DINNER, 0);

    // 14) x2 += ag @ w_prjF
    mma_gemm<<<dim3(3, MTILES), 256, GEMM_SMEM>>>(ag_h, pw_prjF,
        nullptr, p_x2, p_x2, nullptr, 0, BLTOT, CDIM, CDIM, 0);

    // 15) norm2 -> xn2 fp16
    ln_kernel<<<BLTOT / 8, 256>>>(p_x2, norm2_w, norm2_b, xn2_h);

    // 16) MLP fc1 + 17) fc2
    mma_gemm<<<dim3(12, MTILES), 256, GEMM_SMEM>>>(xn2_h, pw_fc1,
        fc1_b, nullptr, nullptr, h1_h, 1536, BLTOT, 1536, CDIM, 1);
    mma_gemm<<<dim3(3, MTILES), 256, GEMM_SMEM>>>(h1_h, pw_fc2,
        fc2_b, p_x2, out, nullptr, 0, BLTOT, CDIM, 1536, 0);
}

// round 16
// speedup vs baseline: 1.1672x; 1.1672x over previous
#include <cuda_runtime.h>
#include <cuda_fp16.h>
#include <math.h>
#include <stdint.h>

// ---------------- problem constants ----------------
#define NB      8
#define HH      56
#define WW      56
#define LSEQ    3136
#define BLTOT   25088
#define CDIM    384
#define DINNER  768
#define DSTATE  64
#define NHM     12
#define DINPROJ 1676
#define CONVDIM 896
#define NHA     12
#define NWIN    512
#define MTILES  196   // BLTOT/128

// ---------------- fp32 scratch ----------------
__device__ float g_xs   [(size_t)BLTOT * DINNER];
__device__ float g_Bm   [(size_t)BLTOT * DSTATE];
__device__ float g_Cm   [(size_t)BLTOT * DSTATE];
__device__ float g_dt   [(size_t)BLTOT * NHM];
__device__ float g_dA   [(size_t)BLTOT * NHM];
__device__ float g_y    [(size_t)BLTOT * DINNER];
__device__ float g_gate [(size_t)BLTOT * NHA];
__device__ float g_x2   [(size_t)BLTOT * CDIM];
__device__ float g_biasF[CDIM];

// ---------------- fp16 activation scratch ----------------
__device__ __half b_zx  [(size_t)BLTOT * DINPROJ];
__device__ __half b_xn  [(size_t)BLTOT * CDIM];
__device__ __half b_g   [(size_t)BLTOT * DINNER];
__device__ __half b_ag  [(size_t)BLTOT * CDIM];
__device__ __half b_h1  [(size_t)BLTOT * 1536];
__device__ __half b_xn2 [(size_t)BLTOT * CDIM];
__device__ __half b_qkv [(size_t)BLTOT * 1152];

// ---------------- fp16 weights ----------------
__device__ __half w_in  [(size_t)DINPROJ * CDIM];   // [N][K] transposed
__device__ __half w_qkv [(size_t)1152 * CDIM];      // transposed
__device__ __half w_fc1 [(size_t)1536 * CDIM];      // transposed
__device__ __half w_fc2 [(size_t)CDIM * 1536];      // transposed
__device__ __half w_fusA[(size_t)CDIM * CDIM];      // F1^T : [n][j]
__device__ __half w_fusB[(size_t)CDIM * CDIM];      // F2^T : [n][j]
__device__ __half w_outD[(size_t)DINNER * CDIM];    // W_out direct copy [768][384]
__device__ __half w_prjD[(size_t)CDIM * CDIM];      // proj_w direct copy
__device__ __half w_outF[(size_t)CDIM * DINNER];    // folded W_out@F1, [N=384][K=768]
__device__ __half w_prjF[(size_t)CDIM * CDIM];      // folded proj_w@F2, [N=384][K=384]

__device__ __forceinline__ uint32_t smem_u32(const void* p) {
    uint32_t a;
    asm("{ .reg .u64 t; cvta.to.shared.u64 t, %1; cvt.u32.u64 %0, t; }" : "=r"(a) : "l"(p));
    return a;
}

// ================= mma.sync fp16 GEMM (round-9 config: 128x128, 2 CTA/SM) =================
#define BKG   64
#define ASTR  72            // BK + 8 pad (fp16); 144B row stride
#define MATSZ (128 * ASTR)  // 9216 elems
#define STAGESZ (2 * MATSZ) // A, B
#define GEMM_SMEM (2 * STAGESZ * 2)  // 73728 bytes

__device__ __forceinline__ void ldsm4(uint32_t& r0, uint32_t& r1, uint32_t& r2, uint32_t& r3, uint32_t a) {
    asm volatile("ldmatrix.sync.aligned.m8n8.x4.shared.b16 {%0,%1,%2,%3}, [%4];"
                 : "=r"(r0), "=r"(r1), "=r"(r2), "=r"(r3) : "r"(a));
}
__device__ __forceinline__ void mma16816(float* c, const uint32_t* a, const uint32_t* b) {
    asm volatile("mma.sync.aligned.m16n8k16.row.col.f32.f16.f16.f32 "
                 "{%0,%1,%2,%3}, {%4,%5,%6,%7}, {%8,%9}, {%0,%1,%2,%3};"
                 : "+f"(c[0]), "+f"(c[1]), "+f"(c[2]), "+f"(c[3])
                 : "r"(a[0]), "r"(a[1]), "r"(a[2]), "r"(a[3]), "r"(b[0]), "r"(b[1]));
}
__device__ __forceinline__ void cpasync16(uint32_t dst, const void* src, uint32_t sz) {
    asm volatile("cp.async.cg.shared.global [%0], [%1], 16, %2;"
                 :: "r"(dst), "l"(src), "r"(sz) : "memory");
}

__global__ void __launch_bounds__(256, 2)
mma_gemm(const __half* __restrict__ Aw, const __half* __restrict__ Bw,
         const float* __restrict__ bias, const float* __restrict__ res,
         float* __restrict__ Cf, __half* __restrict__ Chalf,
         int ldh, int M, int N, int K, int act)
{
    extern __shared__ __align__(16) __half smem[];
    const int tid = threadIdx.x;
    const int wid = tid >> 5, lane = tid & 31;
    const int warp_m = wid & 1, warp_n = wid >> 1;
    const int m0 = blockIdx.y * 128, n0 = blockIdx.x * 128;

    const int lrow = tid >> 1, lseg = tid & 1;
    const bool bvalid = (n0 + lrow) < N;
    const uint32_t sbase = smem_u32(smem);

    float acc[4][4][4];
#pragma unroll
    for (int i = 0; i < 4; i++)
#pragma unroll
        for (int j = 0; j < 4; j++)
#pragma unroll
            for (int e = 0; e < 4; e++) acc[i][j][e] = 0.f;

    const int nch = K / BKG;

    auto load_stage = [&](int ch, int st) {
        const int k0 = ch * BKG;
        uint32_t so = (uint32_t)(st * STAGESZ + lrow * ASTR + lseg * 32) * 2;
        const __half* ga = Aw + (size_t)(m0 + lrow) * K + k0 + lseg * 32;
        const __half* gb = Bw + (size_t)(n0 + lrow) * K + k0 + lseg * 32;
        uint32_t bs = bvalid ? 16u : 0u;
#pragma unroll
        for (int u = 0; u < 4; u++) {
            cpasync16(sbase + so + u * 16,             ga + u * 8, 16u);
            cpasync16(sbase + so + MATSZ * 2 + u * 16, gb + u * 8, bs);
        }
    };

    load_stage(0, 0);
    asm volatile("cp.async.commit_group;" ::: "memory");

    for (int ch = 0; ch < nch; ch++) {
        const int st = ch & 1;
        if (ch + 1 < nch) load_stage(ch + 1, st ^ 1);
        asm volatile("cp.async.commit_group;" ::: "memory");
        asm volatile("cp.async.wait_group 1;" ::: "memory");
        __syncthreads();

        const uint32_t sA = sbase + (uint32_t)(st * STAGESZ) * 2;
        const uint32_t sB = sA + MATSZ * 2;
        const int lr = lane & 15;
        const int lk = (lane >> 4) << 3;

#pragma unroll
        for (int ks = 0; ks < BKG; ks += 16) {
            uint32_t bh[4][2];
#pragma unroll
            for (int np = 0; np < 2; np++) {
                uint32_t off = (uint32_t)((warp_n * 32 + np * 16 + lr) * ASTR + ks + lk) * 2;
                uint32_t r0, r1, r2, r3;
                ldsm4(r0, r1, r2, r3, sB + off);
                bh[np*2+0][0] = r0; bh[np*2+0][1] = r2;
                bh[np*2+1][0] = r1; bh[np*2+1][1] = r3;
            }
#pragma unroll
            for (int mt = 0; mt < 4; mt++) {
                uint32_t off = (uint32_t)((warp_m * 64 + mt * 16 + lr) * ASTR + ks + lk) * 2;
                uint32_t a[4];
                ldsm4(a[0], a[1], a[2], a[3], sA + off);
#pragma unroll
                for (int nt = 0; nt < 4; nt++) mma16816(acc[mt][nt], a, bh[nt]);
            }
        }
        __syncthreads();
    }

    // epilogue
    const int mrow = m0 + warp_m * 64 + (lane >> 2);
    const int ncol = n0 + warp_n * 32 + (lane & 3) * 2;
#pragma unroll
    for (int mt = 0; mt < 4; mt++) {
#pragma unroll
        for (int nt = 0; nt < 4; nt++) {
#pragma unroll
            for (int e = 0; e < 4; e++) {
                int r = mrow + mt * 16 + ((e >> 1) ? 8 : 0);
                int c = ncol + nt * 8 + (e & 1);
                if (c < N) {
                    float v = acc[mt][nt][e];
                    if (bias) v += bias[c];
                    if (act)  v = 0.5f * v * (1.f + erff(v * 0.70710678118654752f));
                    if (res)  v += res[(size_t)r * N + c];
                    if (Cf)    Cf[(size_t)r * N + c] = v;
                    if (Chalf) Chalf[(size_t)r * ldh + c] = __float2half_rn(v);
                }
            }
        }
    }
}

// ---------------- batched weight transpose/copy + fp16 (8 jobs) ----------------
// dst[li] = src[k*N + n] with k=li%K, n=li/K.  (N==1 => direct copy)
struct WJob { const float* src; __half* dst; int K; int N; long off; };
__global__ void wconv_all_kernel(WJob j0, WJob j1, WJob j2, WJob j3, WJob j4, WJob j5,
                                 WJob j6, WJob j7, long total)
{
    long idx = (long)blockIdx.x * blockDim.x + threadIdx.x;
    if (idx >= total) return;
    WJob j;
    if      (idx < j1.off) j = j0;
    else if (idx < j2.off) j = j1;
    else if (idx < j3.off) j = j2;
    else if (idx < j4.off) j = j3;
    else if (idx < j5.off) j = j4;
    else if (idx < j6.off) j = j5;
    else if (idx < j7.off) j = j6;
    else                   j = j7;
    long li = idx - j.off;
    int k = (int)(li % j.K);
    long n = li / j.K;
    j.dst[li] = __float2half_rn(j.src[(size_t)k * j.N + n]);
}

// ---------------- combined bias: biasF[n] = fusion_b[n] + sum_j proj_b[j]*F2[j][n] ----------------
__global__ void biasf_kernel(const float* __restrict__ fusion_b, const float* __restrict__ proj_b,
                             const float* __restrict__ fusion_w, float* __restrict__ outb)
{
    int n = blockIdx.x * blockDim.x + threadIdx.x;
    if (n >= CDIM) return;
    float a = fusion_b[n];
    for (int j = 0; j < CDIM; j++)
        a += proj_b[j] * fusion_w[(size_t)(CDIM + j) * CDIM + n];
    outb[n] = a;
}

// ---------------- LayerNorm (384) -> fp16, warp per row ----------------
__global__ void ln_kernel(const float* __restrict__ x, const float* __restrict__ w,
                          const float* __restrict__ b, __half* __restrict__ oh)
{
    int row  = blockIdx.x * 8 + (threadIdx.x >> 5);
    int lane = threadIdx.x & 31;
    if (row >= BLTOT) return;
    const float* xr = x + (size_t)row * CDIM;
    float v[12];
    float s = 0.f;
#pragma unroll
    for (int i = 0; i < 3; i++) {
        float4 t = *(const float4*)(xr + i * 128 + lane * 4);
        v[i*4+0]=t.x; v[i*4+1]=t.y; v[i*4+2]=t.z; v[i*4+3]=t.w;
        s += t.x + t.y + t.z + t.w;
    }
#pragma unroll
    for (int o = 16; o; o >>= 1) s += __shfl_xor_sync(0xffffffffu, s, o);
    float mu = s * (1.f / CDIM);
    float ss = 0.f;
#pragma unroll
    for (int i = 0; i < 12; i++) { float d = v[i] - mu; ss += d * d; }
#pragma unroll
    for (int o = 16; o; o >>= 1) ss += __shfl_xor_sync(0xffffffffu, ss, o);
    float rstd = rsqrtf(ss * (1.f / CDIM) + 1e-5f);
#pragma unroll
    for (int i = 0; i < 3; i++) {
        int c = i * 128 + lane * 4;
        float4 wv = *(const float4*)(w + c);
        float4 bv = *(const float4*)(b + c);
        size_t o0 = (size_t)row * CDIM + c;
        oh[o0+0] = __float2half_rn((v[i*4+0]-mu)*rstd*wv.x + bv.x);
        oh[o0+1] = __float2half_rn((v[i*4+1]-mu)*rstd*wv.y + bv.y);
        oh[o0+2] = __float2half_rn((v[i*4+2]-mu)*rstd*wv.z + bv.z);
        oh[o0+3] = __float2half_rn((v[i*4+3]-mu)*rstd*wv.w + bv.w);
    }
}

// ---------------- depthwise causal conv(k=4) + SiLU, split (fp16 zx in) ----------------
__global__ void conv_kernel(const __half* __restrict__ zx, const float* __restrict__ cw,
                            const float* __restrict__ cb,
                            float* __restrict__ xs, float* __restrict__ Bout,
                            float* __restrict__ Cout)
{
    long idx = (long)blockIdx.x * blockDim.x + threadIdx.x;
    if (idx >= (long)BLTOT * CONVDIM) return;
    int c  = (int)(idx % CONVDIM);
    long bl = idx / CONVDIM;
    int l  = (int)(bl % LSEQ);
    float acc = cb[c];
    const float w0 = cw[c*4+0], w1 = cw[c*4+1], w2 = cw[c*4+2], w3 = cw[c*4+3];
    const __half* base = zx + (size_t)bl * DINPROJ + DINNER + c;
    if (l >= 3) acc += w0 * __half2float(base[-(size_t)3 * DINPROJ]);
    if (l >= 2) acc += w1 * __half2float(base[-(size_t)2 * DINPROJ]);
    if (l >= 1) acc += w2 * __half2float(base[-(size_t)1 * DINPROJ]);
    acc += w3 * __half2float(base[0]);
    acc = acc / (1.f + expf(-acc));
    if (c < DINNER)            xs[(size_t)bl * DINNER + c] = acc;
    else if (c < DINNER + 64)  Bout[(size_t)bl * 64 + (c - DINNER)] = acc;
    else                       Cout[(size_t)bl * 64 + (c - DINNER - 64)] = acc;
}

// ---------------- dt / dA (fp16 zx in) ----------------
__global__ void dt_kernel(const __half* __restrict__ zx, const float* __restrict__ dtb,
                          const float* __restrict__ Alog,
                          float* __restrict__ dt, float* __restrict__ dA)
{
    long idx = (long)blockIdx.x * blockDim.x + threadIdx.x;
    if (idx >= (long)BLTOT * NHM) return;
    int h = (int)(idx % NHM);
    long bl = idx / NHM;
    float x = __half2float(zx[(size_t)bl * DINPROJ + (DINPROJ - NHM) + h]) + dtb[h];
    float sp = (x > 20.f) ? x : log1pf(expf(x));
    float A  = -expf(Alog[h]);
    dt[idx] = sp;
    dA[idx] = expf(sp * A);
}

// ---------------- selective scan (round-6 winner) ----------------
__global__ void __launch_bounds__(512, 1)
scan_kernel(const float* __restrict__ xs, const float* __restrict__ Bm,
            const float* __restrict__ Cm, const float* __restrict__ dt,
            const float* __restrict__ dA, const float* __restrict__ Dp,
            float* __restrict__ y)
{
    const int T = 16;
    int b = blockIdx.x / NHM;
    int h = blockIdx.x % NHM;
    int tid = threadIdx.x;
    int p  = tid >> 3;
    int nc = tid & 7;
    int n0 = nc * 8;
    __shared__ float sB[T][64], sC[T][64], sX[T][64], sDt[T], sDa[T];
    float s[8];
#pragma unroll
    for (int j = 0; j < 8; j++) s[j] = 0.f;
    float Dh = Dp[h];
    size_t base = (size_t)b * LSEQ;

    for (int l0 = 0; l0 < LSEQ; l0 += T) {
        __syncthreads();
        for (int idx = tid; idx < T * 64; idx += 512) {
            int t = idx >> 6, j = idx & 63;
            size_t r = base + l0 + t;
            sB[t][j] = Bm[r * 64 + j];
            sC[t][j] = Cm[r * 64 + j];
            sX[t][j] = xs[r * DINNER + h * 64 + j];
        }
        if (tid < T) {
            size_t r = base + l0 + tid;
            sDt[tid] = dt[r * NHM + h];
            sDa[tid] = dA[r * NHM + h];
        }
        __syncthreads();
#pragma unroll 4
        for (int t = 0; t < T; t++) {
            float da  = sDa[t];
            float dtx = sDt[t] * sX[t][p];
            float part = 0.f;
#pragma unroll
            for (int j = 0; j < 8; j++) {
                s[j] = s[j] * da + dtx * sB[t][n0 + j];
                part += s[j] * sC[t][n0 + j];
            }
            part += __shfl_xor_sync(0xffffffffu, part, 1);
            part += __shfl_xor_sync(0xffffffffu, part, 2);
            part += __shfl_xor_sync(0xffffffffu, part, 4);
            if (nc == 0)
                y[(base + l0 + t) * DINNER + h * 64 + p] = part + Dh * sX[t][p];
        }
    }
}

// ---------------- gated rmsnorm (768) -> fp16 (fp16 z in) ----------------
__global__ void rmsgate_kernel(const float* __restrict__ y, const __half* __restrict__ zx,
                               const float* __restrict__ mw, __half* __restrict__ oh)
{
    int row  = blockIdx.x * 8 + (threadIdx.x >> 5);
    int lane = threadIdx.x & 31;
    if (row >= BLTOT) return;
    const float* yr = y  + (size_t)row * DINNER;
    const __half* zr = zx + (size_t)row * DINPROJ;
    float g[24];
    float ss = 0.f;
#pragma unroll
    for (int i = 0; i < 6; i++) {
        int c = i * 128 + lane * 4;
        float4 yv = *(const float4*)(yr + c);
        __half2 zp0 = *(const __half2*)(zr + c);
        __half2 zp1 = *(const __half2*)(zr + c + 2);
        float zf0 = __half2float(zp0.x), zf1 = __half2float(zp0.y);
        float zf2 = __half2float(zp1.x), zf3 = __half2float(zp1.y);
        float z0 = zf0 / (1.f + expf(-zf0));
        float z1 = zf1 / (1.f + expf(-zf1));
        float z2 = zf2 / (1.f + expf(-zf2));
        float z3 = zf3 / (1.f + expf(-zf3));
        g[i*4+0] = yv.x * z0; g[i*4+1] = yv.y * z1;
        g[i*4+2] = yv.z * z2; g[i*4+3] = yv.w * z3;
        ss += g[i*4+0]*g[i*4+0] + g[i*4+1]*g[i*4+1] + g[i*4+2]*g[i*4+2] + g[i*4+3]*g[i*4+3];
    }
#pragma unroll
    for (int o = 16; o; o >>= 1) ss += __shfl_xor_sync(0xffffffffu, ss, o);
    float rstd = rsqrtf(ss * (1.f / DINNER) + 1e-5f);
#pragma unroll
    for (int i = 0; i < 6; i++) {
        int c = i * 128 + lane * 4;
        float4 wv = *(const float4*)(mw + c);
        size_t o0 = (size_t)row * DINNER + c;
        oh[o0+0] = __float2half_rn(g[i*4+0]*rstd*wv.x);
        oh[o0+1] = __float2half_rn(g[i*4+1]*rstd*wv.y);
        oh[o0+2] = __float2half_rn(g[i*4+2]*rstd*wv.z);
        oh[o0+3] = __float2half_rn(g[i*4+3]*rstd*wv.w);
    }
}

// ---------------- attention gate (warp per row, 12 heads, fp16 xn) ----------------
__global__ void gate_kernel(const __half* __restrict__ xn, const float* __restrict__ gw,
                            const float* __restrict__ gb, float* __restrict__ out)
{
    int row  = blockIdx.x * 8 + (threadIdx.x >> 5);
    int lane = threadIdx.x & 31;
    if (row >= BLTOT) return;
    const __half* xr = xn + (size_t)row * CDIM;
    float acc[12];
#pragma unroll
    for (int h = 0; h < 12; h++) acc[h] = 0.f;
    for (int c = lane; c < CDIM; c += 32) {
        float xv = __half2float(xr[c]);
        const float* g = gw + c * 12;
#pragma unroll
        for (int h = 0; h < 12; h++) acc[h] += xv * g[h];
    }
#pragma unroll
    for (int h = 0; h < 12; h++)
#pragma unroll
        for (int o = 16; o; o >>= 1) acc[h] += __shfl_xor_sync(0xffffffffu, acc[h], o);
    if (lane == 0) {
#pragma unroll
        for (int h = 0; h < 12; h++) {
            float a = acc[h] + gb[h];
            out[(size_t)row * NHA + h] = 1.f / (1.f + expf(-a));
        }
    }
}

// ---------------- window attention (fp16 qkv) -> gated fp16 output ----------------
__global__ void __launch_bounds__(64)
attn_kernel(const __half* __restrict__ qkv, const float* __restrict__ gate,
            __half* __restrict__ oh)
{
    int wid = blockIdx.x;
    int h   = blockIdx.y;
    int b   = wid >> 6;
    int rem = wid & 63;
    int wh  = rem >> 3;
    int ww  = rem & 7;
    __shared__ float q[49][33], k[49][33], v[49][33];
    int tid = threadIdx.x;
    for (int idx = tid; idx < 49 * 32; idx += 64) {
        int i = idx >> 5, d = idx & 31;
        int r = i / 7, c = i % 7;
        int l = (wh * 7 + r) * WW + ww * 7 + c;
        size_t rowoff = ((size_t)b * LSEQ + l) * 1152 + h * 32 + d;
        q[i][d] = __half2float(qkv[rowoff]) * 0.17677669529663687f;
        k[i][d] = __half2float(qkv[rowoff + 384]);
        v[i][d] = __half2float(qkv[rowoff + 768]);
    }
    __syncthreads();
    if (tid < 49) {
        int i = tid;
        int r = i / 7, c = i % 7;
        int l = (wh * 7 + r) * WW + ww * 7 + c;
        float sc[49];
        float mx = -1e30f;
        for (int j = 0; j < 49; j++) {
            float a = 0.f;
#pragma unroll
            for (int d = 0; d < 32; d++) a += q[i][d] * k[j][d];
            sc[j] = a;
            mx = fmaxf(mx, a);
        }
        float sum = 0.f;
        for (int j = 0; j < 49; j++) { sc[j] = expf(sc[j] - mx); sum += sc[j]; }
        float ga = gate[((size_t)b * LSEQ + l) * NHA + h];
        float inv = ga / sum;
        size_t o0 = ((size_t)b * LSEQ + l) * CDIM + h * 32;
#pragma unroll
        for (int d = 0; d < 32; d++) {
            float o = 0.f;
            for (int j = 0; j < 49; j++) o += sc[j] * v[j][d];
            oh[o0 + d] = __float2half_rn(o * inv);
        }
    }
}

// ---------------- launch ----------------
static void* devptr(const void* sym) {
    void* p = nullptr;
    cudaGetSymbolAddress(&p, sym);
    return p;
}

extern "C" void kernel_launch(void* const* d_in, const int* in_sizes, int n_in,
                              void* d_out, int out_size)
{
    const float* x       = (const float*)d_in[0];
    const float* norm1_w = (const float*)d_in[1];
    const float* norm1_b = (const float*)d_in[2];
    const float* W_in    = (const float*)d_in[3];
    const float* conv_w  = (const float*)d_in[4];
    const float* conv_b  = (const float*)d_in[5];
    const float* dt_bias = (const float*)d_in[6];
    const float* A_log   = (const float*)d_in[7];
    const float* Dp      = (const float*)d_in[8];
    const float* mnorm_w = (const float*)d_in[9];
    const float* W_out   = (const float*)d_in[10];
    const float* qkv_w   = (const float*)d_in[11];
    const float* qkv_b   = (const float*)d_in[12];
    const float* gate_w  = (const float*)d_in[13];
    const float* gate_b  = (const float*)d_in[14];
    const float* proj_w  = (const float*)d_in[15];
    const float* proj_b  = (const float*)d_in[16];
    const float* fusion_w= (const float*)d_in[17];
    const float* fusion_b= (const float*)d_in[18];
    const float* norm2_w = (const float*)d_in[19];
    const float* norm2_b = (const float*)d_in[20];
    const float* fc1_w   = (const float*)d_in[21];
    const float* fc1_b   = (const float*)d_in[22];
    const float* fc2_w   = (const float*)d_in[23];
    const float* fc2_b   = (const float*)d_in[24];
    float* out = (float*)d_out;

    cudaFuncSetAttribute(mma_gemm, cudaFuncAttributeMaxDynamicSharedMemorySize, GEMM_SMEM);

    float* p_xs  = (float*)devptr(g_xs);
    float* p_Bm  = (float*)devptr(g_Bm);
    float* p_Cm  = (float*)devptr(g_Cm);
    float* p_dt  = (float*)devptr(g_dt);
    float* p_dA  = (float*)devptr(g_dA);
    float* p_y   = (float*)devptr(g_y);
    float* p_gt  = (float*)devptr(g_gate);
    float* p_x2  = (float*)devptr(g_x2);
    float* p_bF  = (float*)devptr(g_biasF);

    __half* zx_h  = (__half*)devptr(b_zx);
    __half* xn_h  = (__half*)devptr(b_xn);
    __half* gh    = (__half*)devptr(b_g);
    __half* ag_h  = (__half*)devptr(b_ag);
    __half* h1_h  = (__half*)devptr(b_h1);
    __half* xn2_h = (__half*)devptr(b_xn2);
    __half* qkv_h = (__half*)devptr(b_qkv);

    __half* pw_in   = (__half*)devptr(w_in);
    __half* pw_qkv  = (__half*)devptr(w_qkv);
    __half* pw_fc1  = (__half*)devptr(w_fc1);
    __half* pw_fc2  = (__half*)devptr(w_fc2);
    __half* pw_fusA = (__half*)devptr(w_fusA);
    __half* pw_fusB = (__half*)devptr(w_fusB);
    __half* pw_outD = (__half*)devptr(w_outD);
    __half* pw_prjD = (__half*)devptr(w_prjD);
    __half* pw_outF = (__half*)devptr(w_outF);
    __half* pw_prjF = (__half*)devptr(w_prjF);

    // 1) batched weight transpose/copy + fp16 (ONE kernel, 8 jobs)
    {
        WJob j0{W_in,                 pw_in,   CDIM,            DINPROJ, 0};  // transpose
        WJob j1{qkv_w,                pw_qkv,  CDIM,            1152,    0};  // transpose
        WJob j2{fc1_w,                pw_fc1,  CDIM,            1536,    0};  // transpose
        WJob j3{fc2_w,                pw_fc2,  1536,            CDIM,    0};  // transpose
        WJob j4{fusion_w,             pw_fusA, CDIM,            CDIM,    0};  // F1^T
        WJob j5{fusion_w + CDIM*CDIM, pw_fusB, CDIM,            CDIM,    0};  // F2^T
        WJob j6{W_out,                pw_outD, DINNER * CDIM,   1,       0};  // direct copy
        WJob j7{proj_w,               pw_prjD, CDIM * CDIM,     1,       0};  // direct copy
        long off = 0;
        j0.off = off; off += (long)j0.K * j0.N;
        j1.off = off; off += (long)j1.K * j1.N;
        j2.off = off; off += (long)j2.K * j2.N;
        j3.off = off; off += (long)j3.K * j3.N;
        j4.off = off; off += (long)j4.K * j4.N;
        j5.off = off; off += (long)j5.K * j5.N;
        j6.off = off; off += (long)j6.K * j6.N;
        j7.off = off; off += (long)j7.K * j7.N;
        wconv_all_kernel<<<(unsigned)((off + 255) / 256), 256>>>(j0, j1, j2, j3, j4, j5, j6, j7, off);
    }

    // 2) combined bias + weight folds (tiny GEMMs)
    biasf_kernel<<<2, 192>>>(fusion_b, proj_b, fusion_w, p_bF);
    //    w_outF[n][k] = sum_j F1[j][n] * W_out[k][j]
    mma_gemm<<<dim3(6, 3), 256, GEMM_SMEM>>>(pw_fusA, pw_outD,
        nullptr, nullptr, nullptr, pw_outF, DINNER, CDIM, DINNER, CDIM, 0);
    //    w_prjF[n][k] = sum_j F2[j][n] * proj_w[k][j]
    mma_gemm<<<dim3(3, 3), 256, GEMM_SMEM>>>(pw_fusB, pw_prjD,
        nullptr, nullptr, nullptr, pw_prjF, CDIM, CDIM, CDIM, CDIM, 0);

    // 3) norm1 -> fp16
    ln_kernel<<<BLTOT / 8, 256>>>(x, norm1_w, norm1_b, xn_h);

    // 4) attention gate
    gate_kernel<<<BLTOT / 8, 256>>>(xn_h, gate_w, gate_b, p_gt);

    // 5) qkv -> fp16 (bias fused)
    mma_gemm<<<dim3(9, MTILES), 256, GEMM_SMEM>>>(xn_h, pw_qkv,
        qkv_b, nullptr, nullptr, qkv_h, 1152, BLTOT, 1152, CDIM, 0);

    // 6) window attention -> attng fp16
    attn_kernel<<<dim3(NWIN, NHA), 64>>>(qkv_h, p_gt, ag_h);

    // 7) in_proj -> zx (fp16)
    mma_gemm<<<dim3(14, MTILES), 256, GEMM_SMEM>>>(xn_h, pw_in,
        nullptr, nullptr, nullptr, zx_h, DINPROJ, BLTOT, DINPROJ, CDIM, 0);

    // 8) conv + 9) dt
    {
        long tot = (long)BLTOT * CONVDIM;
        conv_kernel<<<(unsigned)((tot + 255) / 256), 256>>>(zx_h, conv_w, conv_b, p_xs, p_Bm, p_Cm);
        long tot2 = (long)BLTOT * NHM;
        dt_kernel<<<(unsigned)((tot2 + 255) / 256), 256>>>(zx_h, dt_bias, A_log, p_dt, p_dA);
    }

    // 10) scan
    scan_kernel<<<NB * NHM, 512>>>(p_xs, p_Bm, p_Cm, p_dt, p_dA, Dp, p_y);

    // 11) gated rmsnorm -> g fp16
    rmsgate_kernel<<<BLTOT / 8, 256>>>(p_y, zx_h, mnorm_w, gh);

    // 12) x2 = x + g @ w_outF + biasF   (fusion folded into out_proj)
    mma_gemm<<<dim3(3, MTILES), 256, GEMM_SMEM>>>(gh, pw_outF,
        p_bF, x, p_x2, nullptr, 0, BLTOT, CDIM, DINNER, 0);

    // 13) x2 += ag @ w_prjF            (fusion folded into attn proj)
    mma_gemm<<<dim3(3, MTILES), 256, GEMM_SMEM>>>(ag_h, pw_prjF,
        nullptr, p_x2, p_x2, nullptr, 0, BLTOT, CDIM, CDIM, 0);

    // 14) norm2 -> xn2 fp16
    ln_kernel<<<BLTOT / 8, 256>>>(p_x2, norm2_w, norm2_b, xn2_h);

    // 15) MLP fc1 + 16) fc2
    mma_gemm<<<dim3(12, MTILES), 256, GEMM_SMEM>>>(xn2_h, pw_fc1,
        fc1_b, nullptr, nullptr, h1_h, 1536, BLTOT, 1536, CDIM, 1);
    mma_gemm<<<dim3(3, MTILES), 256, GEMM_SMEM>>>(h1_h, pw_fc2,
        fc2_b, p_x2, out, nullptr, 0, BLTOT, CDIM, 1536, 0);
}

// round 17
// speedup vs baseline: 1.1843x; 1.0146x over previous
#include <cuda_runtime.h>
#include <cuda_fp16.h>
#include <math.h>
#include <stdint.h>

// ---------------- problem constants ----------------
#define NB      8
#define HH      56
#define WW      56
#define LSEQ    3136
#define BLTOT   25088
#define CDIM    384
#define DINNER  768
#define DSTATE  64
#define NHM     12
#define DINPROJ 1676
#define CONVDIM 896
#define NHA     12
#define NWIN    512
#define MTILES  196   // BLTOT/128
#define KCAT    1152  // 768 + 384

// ---------------- fp32 scratch ----------------
__device__ float g_xs   [(size_t)BLTOT * DINNER];
__device__ float g_Bm   [(size_t)BLTOT * DSTATE];
__device__ float g_Cm   [(size_t)BLTOT * DSTATE];
__device__ float g_dt   [(size_t)BLTOT * NHM];
__device__ float g_dA   [(size_t)BLTOT * NHM];
__device__ float g_y    [(size_t)BLTOT * DINNER];
__device__ float g_gate [(size_t)BLTOT * NHA];
__device__ float g_x2   [(size_t)BLTOT * CDIM];
__device__ float g_biasF[CDIM];

// ---------------- fp16 activation scratch ----------------
__device__ __half b_zx  [(size_t)BLTOT * DINPROJ];
__device__ __half b_xn  [(size_t)BLTOT * CDIM];
__device__ __half b_cat [(size_t)BLTOT * KCAT];     // [g (768) | gated attn (384)]
__device__ __half b_h1  [(size_t)BLTOT * 1536];
__device__ __half b_xn2 [(size_t)BLTOT * CDIM];
__device__ __half b_qkv [(size_t)BLTOT * 1152];

// ---------------- fp16 weights ----------------
__device__ __half w_in  [(size_t)DINPROJ * CDIM];   // [N][K] transposed
__device__ __half w_qkv [(size_t)1152 * CDIM];      // transposed
__device__ __half w_fc1 [(size_t)1536 * CDIM];      // transposed
__device__ __half w_fc2 [(size_t)CDIM * 1536];      // transposed
__device__ __half w_fusA[(size_t)CDIM * CDIM];      // F1^T : [n][j]
__device__ __half w_fusB[(size_t)CDIM * CDIM];      // F2^T : [n][j]
__device__ __half w_outD[(size_t)DINNER * CDIM];    // W_out direct copy [768][384]
__device__ __half w_prjD[(size_t)CDIM * CDIM];      // proj_w direct copy
__device__ __half w_catF[(size_t)CDIM * KCAT];      // [folded W_out@F1 | folded proj@F2], [384][1152]

__device__ __forceinline__ uint32_t smem_u32(const void* p) {
    uint32_t a;
    asm("{ .reg .u64 t; cvta.to.shared.u64 t, %1; cvt.u32.u64 %0, t; }" : "=r"(a) : "l"(p));
    return a;
}

// ================= mma.sync fp16 GEMM (round-9 config: 128x128, 2 CTA/SM) =================
#define BKG   64
#define ASTR  72            // BK + 8 pad (fp16); 144B row stride
#define MATSZ (128 * ASTR)  // 9216 elems
#define STAGESZ (2 * MATSZ) // A, B
#define GEMM_SMEM (2 * STAGESZ * 2)  // 73728 bytes

__device__ __forceinline__ void ldsm4(uint32_t& r0, uint32_t& r1, uint32_t& r2, uint32_t& r3, uint32_t a) {
    asm volatile("ldmatrix.sync.aligned.m8n8.x4.shared.b16 {%0,%1,%2,%3}, [%4];"
                 : "=r"(r0), "=r"(r1), "=r"(r2), "=r"(r3) : "r"(a));
}
__device__ __forceinline__ void mma16816(float* c, const uint32_t* a, const uint32_t* b) {
    asm volatile("mma.sync.aligned.m16n8k16.row.col.f32.f16.f16.f32 "
                 "{%0,%1,%2,%3}, {%4,%5,%6,%7}, {%8,%9}, {%0,%1,%2,%3};"
                 : "+f"(c[0]), "+f"(c[1]), "+f"(c[2]), "+f"(c[3])
                 : "r"(a[0]), "r"(a[1]), "r"(a[2]), "r"(a[3]), "r"(b[0]), "r"(b[1]));
}
__device__ __forceinline__ void cpasync16(uint32_t dst, const void* src, uint32_t sz) {
    asm volatile("cp.async.cg.shared.global [%0], [%1], 16, %2;"
                 :: "r"(dst), "l"(src), "r"(sz) : "memory");
}

__global__ void __launch_bounds__(256, 2)
mma_gemm(const __half* __restrict__ Aw, const __half* __restrict__ Bw,
         const float* __restrict__ bias, const float* __restrict__ res,
         float* __restrict__ Cf, __half* __restrict__ Chalf,
         int ldh, int M, int N, int K, int act)
{
    extern __shared__ __align__(16) __half smem[];
    const int tid = threadIdx.x;
    const int wid = tid >> 5, lane = tid & 31;
    const int warp_m = wid & 1, warp_n = wid >> 1;
    const int m0 = blockIdx.y * 128, n0 = blockIdx.x * 128;

    const int lrow = tid >> 1, lseg = tid & 1;
    const bool bvalid = (n0 + lrow) < N;
    const uint32_t sbase = smem_u32(smem);

    float acc[4][4][4];
#pragma unroll
    for (int i = 0; i < 4; i++)
#pragma unroll
        for (int j = 0; j < 4; j++)
#pragma unroll
            for (int e = 0; e < 4; e++) acc[i][j][e] = 0.f;

    const int nch = K / BKG;

    auto load_stage = [&](int ch, int st) {
        const int k0 = ch * BKG;
        uint32_t so = (uint32_t)(st * STAGESZ + lrow * ASTR + lseg * 32) * 2;
        const __half* ga = Aw + (size_t)(m0 + lrow) * K + k0 + lseg * 32;
        const __half* gb = Bw + (size_t)(n0 + lrow) * K + k0 + lseg * 32;
        uint32_t bs = bvalid ? 16u : 0u;
#pragma unroll
        for (int u = 0; u < 4; u++) {
            cpasync16(sbase + so + u * 16,             ga + u * 8, 16u);
            cpasync16(sbase + so + MATSZ * 2 + u * 16, gb + u * 8, bs);
        }
    };

    load_stage(0, 0);
    asm volatile("cp.async.commit_group;" ::: "memory");

    for (int ch = 0; ch < nch; ch++) {
        const int st = ch & 1;
        if (ch + 1 < nch) load_stage(ch + 1, st ^ 1);
        asm volatile("cp.async.commit_group;" ::: "memory");
        asm volatile("cp.async.wait_group 1;" ::: "memory");
        __syncthreads();

        const uint32_t sA = sbase + (uint32_t)(st * STAGESZ) * 2;
        const uint32_t sB = sA + MATSZ * 2;
        const int lr = lane & 15;
        const int lk = (lane >> 4) << 3;

#pragma unroll
        for (int ks = 0; ks < BKG; ks += 16) {
            uint32_t bh[4][2];
#pragma unroll
            for (int np = 0; np < 2; np++) {
                uint32_t off = (uint32_t)((warp_n * 32 + np * 16 + lr) * ASTR + ks + lk) * 2;
                uint32_t r0, r1, r2, r3;
                ldsm4(r0, r1, r2, r3, sB + off);
                bh[np*2+0][0] = r0; bh[np*2+0][1] = r2;
                bh[np*2+1][0] = r1; bh[np*2+1][1] = r3;
            }
#pragma unroll
            for (int mt = 0; mt < 4; mt++) {
                uint32_t off = (uint32_t)((warp_m * 64 + mt * 16 + lr) * ASTR + ks + lk) * 2;
                uint32_t a[4];
                ldsm4(a[0], a[1], a[2], a[3], sA + off);
#pragma unroll
                for (int nt = 0; nt < 4; nt++) mma16816(acc[mt][nt], a, bh[nt]);
            }
        }
        __syncthreads();
    }

    // epilogue
    const int mrow = m0 + warp_m * 64 + (lane >> 2);
    const int ncol = n0 + warp_n * 32 + (lane & 3) * 2;
#pragma unroll
    for (int mt = 0; mt < 4; mt++) {
#pragma unroll
        for (int nt = 0; nt < 4; nt++) {
#pragma unroll
            for (int e = 0; e < 4; e++) {
                int r = mrow + mt * 16 + ((e >> 1) ? 8 : 0);
                int c = ncol + nt * 8 + (e & 1);
                if (c < N) {
                    float v = acc[mt][nt][e];
                    if (bias) v += bias[c];
                    if (act)  v = 0.5f * v * (1.f + erff(v * 0.70710678118654752f));
                    if (res)  v += res[(size_t)r * N + c];
                    if (Cf)    Cf[(size_t)r * N + c] = v;
                    if (Chalf) Chalf[(size_t)r * ldh + c] = __float2half_rn(v);
                }
            }
        }
    }
}

// ---------------- batched weight transpose/copy + fp16 (8 jobs) ----------------
// dst[li] = src[k*N + n] with k=li%K, n=li/K.  (N==1 => direct copy)
struct WJob { const float* src; __half* dst; int K; int N; long off; };
__global__ void wconv_all_kernel(WJob j0, WJob j1, WJob j2, WJob j3, WJob j4, WJob j5,
                                 WJob j6, WJob j7, long total)
{
    long idx = (long)blockIdx.x * blockDim.x + threadIdx.x;
    if (idx >= total) return;
    WJob j;
    if      (idx < j1.off) j = j0;
    else if (idx < j2.off) j = j1;
    else if (idx < j3.off) j = j2;
    else if (idx < j4.off) j = j3;
    else if (idx < j5.off) j = j4;
    else if (idx < j6.off) j = j5;
    else if (idx < j7.off) j = j6;
    else                   j = j7;
    long li = idx - j.off;
    int k = (int)(li % j.K);
    long n = li / j.K;
    j.dst[li] = __float2half_rn(j.src[(size_t)k * j.N + n]);
}

// ---------------- combined bias (warp per n): biasF[n] = fusion_b[n] + sum_j proj_b[j]*F2[j][n] ----------------
__global__ void biasf_kernel(const float* __restrict__ fusion_b, const float* __restrict__ proj_b,
                             const float* __restrict__ fusion_w, float* __restrict__ outb)
{
    int warp = (blockIdx.x * blockDim.x + threadIdx.x) >> 5;
    int lane = threadIdx.x & 31;
    if (warp >= CDIM) return;
    float a = 0.f;
    for (int j = lane; j < CDIM; j += 32)
        a += proj_b[j] * fusion_w[(size_t)(CDIM + j) * CDIM + warp];
#pragma unroll
    for (int o = 16; o; o >>= 1) a += __shfl_xor_sync(0xffffffffu, a, o);
    if (lane == 0) outb[warp] = a + fusion_b[warp];
}

// ---------------- LayerNorm (384) -> fp16, warp per row ----------------
__global__ void ln_kernel(const float* __restrict__ x, const float* __restrict__ w,
                          const float* __restrict__ b, __half* __restrict__ oh)
{
    int row  = blockIdx.x * 8 + (threadIdx.x >> 5);
    int lane = threadIdx.x & 31;
    if (row >= BLTOT) return;
    const float* xr = x + (size_t)row * CDIM;
    float v[12];
    float s = 0.f;
#pragma unroll
    for (int i = 0; i < 3; i++) {
        float4 t = *(const float4*)(xr + i * 128 + lane * 4);
        v[i*4+0]=t.x; v[i*4+1]=t.y; v[i*4+2]=t.z; v[i*4+3]=t.w;
        s += t.x + t.y + t.z + t.w;
    }
#pragma unroll
    for (int o = 16; o; o >>= 1) s += __shfl_xor_sync(0xffffffffu, s, o);
    float mu = s * (1.f / CDIM);
    float ss = 0.f;
#pragma unroll
    for (int i = 0; i < 12; i++) { float d = v[i] - mu; ss += d * d; }
#pragma unroll
    for (int o = 16; o; o >>= 1) ss += __shfl_xor_sync(0xffffffffu, ss, o);
    float rstd = rsqrtf(ss * (1.f / CDIM) + 1e-5f);
#pragma unroll
    for (int i = 0; i < 3; i++) {
        int c = i * 128 + lane * 4;
        float4 wv = *(const float4*)(w + c);
        float4 bv = *(const float4*)(b + c);
        size_t o0 = (size_t)row * CDIM + c;
        oh[o0+0] = __float2half_rn((v[i*4+0]-mu)*rstd*wv.x + bv.x);
        oh[o0+1] = __float2half_rn((v[i*4+1]-mu)*rstd*wv.y + bv.y);
        oh[o0+2] = __float2half_rn((v[i*4+2]-mu)*rstd*wv.z + bv.z);
        oh[o0+3] = __float2half_rn((v[i*4+3]-mu)*rstd*wv.w + bv.w);
    }
}

// ---------------- depthwise causal conv(k=4) + SiLU, split (fp16 zx in) ----------------
__global__ void conv_kernel(const __half* __restrict__ zx, const float* __restrict__ cw,
                            const float* __restrict__ cb,
                            float* __restrict__ xs, float* __restrict__ Bout,
                            float* __restrict__ Cout)
{
    long idx = (long)blockIdx.x * blockDim.x + threadIdx.x;
    if (idx >= (long)BLTOT * CONVDIM) return;
    int c  = (int)(idx % CONVDIM);
    long bl = idx / CONVDIM;
    int l  = (int)(bl % LSEQ);
    float acc = cb[c];
    const float w0 = cw[c*4+0], w1 = cw[c*4+1], w2 = cw[c*4+2], w3 = cw[c*4+3];
    const __half* base = zx + (size_t)bl * DINPROJ + DINNER + c;
    if (l >= 3) acc += w0 * __half2float(base[-(size_t)3 * DINPROJ]);
    if (l >= 2) acc += w1 * __half2float(base[-(size_t)2 * DINPROJ]);
    if (l >= 1) acc += w2 * __half2float(base[-(size_t)1 * DINPROJ]);
    acc += w3 * __half2float(base[0]);
    acc = acc / (1.f + expf(-acc));
    if (c < DINNER)            xs[(size_t)bl * DINNER + c] = acc;
    else if (c < DINNER + 64)  Bout[(size_t)bl * 64 + (c - DINNER)] = acc;
    else                       Cout[(size_t)bl * 64 + (c - DINNER - 64)] = acc;
}

// ---------------- dt / dA (fp16 zx in) ----------------
__global__ void dt_kernel(const __half* __restrict__ zx, const float* __restrict__ dtb,
                          const float* __restrict__ Alog,
                          float* __restrict__ dt, float* __restrict__ dA)
{
    long idx = (long)blockIdx.x * blockDim.x + threadIdx.x;
    if (idx >= (long)BLTOT * NHM) return;
    int h = (int)(idx % NHM);
    long bl = idx / NHM;
    float x = __half2float(zx[(size_t)bl * DINPROJ + (DINPROJ - NHM) + h]) + dtb[h];
    float sp = (x > 20.f) ? x : log1pf(expf(x));
    float A  = -expf(Alog[h]);
    dt[idx] = sp;
    dA[idx] = expf(sp * A);
}

// ---------------- selective scan (round-6 winner) ----------------
__global__ void __launch_bounds__(512, 1)
scan_kernel(const float* __restrict__ xs, const float* __restrict__ Bm,
            const float* __restrict__ Cm, const float* __restrict__ dt,
            const float* __restrict__ dA, const float* __restrict__ Dp,
            float* __restrict__ y)
{
    const int T = 16;
    int b = blockIdx.x / NHM;
    int h = blockIdx.x % NHM;
    int tid = threadIdx.x;
    int p  = tid >> 3;
    int nc = tid & 7;
    int n0 = nc * 8;
    __shared__ float sB[T][64], sC[T][64], sX[T][64], sDt[T], sDa[T];
    float s[8];
#pragma unroll
    for (int j = 0; j < 8; j++) s[j] = 0.f;
    float Dh = Dp[h];
    size_t base = (size_t)b * LSEQ;

    for (int l0 = 0; l0 < LSEQ; l0 += T) {
        __syncthreads();
        for (int idx = tid; idx < T * 64; idx += 512) {
            int t = idx >> 6, j = idx & 63;
            size_t r = base + l0 + t;
            sB[t][j] = Bm[r * 64 + j];
            sC[t][j] = Cm[r * 64 + j];
            sX[t][j] = xs[r * DINNER + h * 64 + j];
        }
        if (tid < T) {
            size_t r = base + l0 + tid;
            sDt[tid] = dt[r * NHM + h];
            sDa[tid] = dA[r * NHM + h];
        }
        __syncthreads();
#pragma unroll 4
        for (int t = 0; t < T; t++) {
            float da  = sDa[t];
            float dtx = sDt[t] * sX[t][p];
            float part = 0.f;
#pragma unroll
            for (int j = 0; j < 8; j++) {
                s[j] = s[j] * da + dtx * sB[t][n0 + j];
                part += s[j] * sC[t][n0 + j];
            }
            part += __shfl_xor_sync(0xffffffffu, part, 1);
            part += __shfl_xor_sync(0xffffffffu, part, 2);
            part += __shfl_xor_sync(0xffffffffu, part, 4);
            if (nc == 0)
                y[(base + l0 + t) * DINNER + h * 64 + p] = part + Dh * sX[t][p];
        }
    }
}

// ---------------- gated rmsnorm (768) -> fp16 into cat[:, 0:768] (row stride 1152) ----------------
__global__ void rmsgate_kernel(const float* __restrict__ y, const __half* __restrict__ zx,
                               const float* __restrict__ mw, __half* __restrict__ oh)
{
    int row  = blockIdx.x * 8 + (threadIdx.x >> 5);
    int lane = threadIdx.x & 31;
    if (row >= BLTOT) return;
    const float* yr = y  + (size_t)row * DINNER;
    const __half* zr = zx + (size_t)row * DINPROJ;
    float g[24];
    float ss = 0.f;
#pragma unroll
    for (int i = 0; i < 6; i++) {
        int c = i * 128 + lane * 4;
        float4 yv = *(const float4*)(yr + c);
        __half2 zp0 = *(const __half2*)(zr + c);
        __half2 zp1 = *(const __half2*)(zr + c + 2);
        float zf0 = __half2float(zp0.x), zf1 = __half2float(zp0.y);
        float zf2 = __half2float(zp1.x), zf3 = __half2float(zp1.y);
        float z0 = zf0 / (1.f + expf(-zf0));
        float z1 = zf1 / (1.f + expf(-zf1));
        float z2 = zf2 / (1.f + expf(-zf2));
        float z3 = zf3 / (1.f + expf(-zf3));
        g[i*4+0] = yv.x * z0; g[i*4+1] = yv.y * z1;
        g[i*4+2] = yv.z * z2; g[i*4+3] = yv.w * z3;
        ss += g[i*4+0]*g[i*4+0] + g[i*4+1]*g[i*4+1] + g[i*4+2]*g[i*4+2] + g[i*4+3]*g[i*4+3];
    }
#pragma unroll
    for (int o = 16; o; o >>= 1) ss += __shfl_xor_sync(0xffffffffu, ss, o);
    float rstd = rsqrtf(ss * (1.f / DINNER) + 1e-5f);
#pragma unroll
    for (int i = 0; i < 6; i++) {
        int c = i * 128 + lane * 4;
        float4 wv = *(const float4*)(mw + c);
        size_t o0 = (size_t)row * KCAT + c;
        oh[o0+0] = __float2half_rn(g[i*4+0]*rstd*wv.x);
        oh[o0+1] = __float2half_rn(g[i*4+1]*rstd*wv.y);
        oh[o0+2] = __float2half_rn(g[i*4+2]*rstd*wv.z);
        oh[o0+3] = __float2half_rn(g[i*4+3]*rstd*wv.w);
    }
}

// ---------------- attention gate (warp per row, 12 heads, fp16 xn) ----------------
__global__ void gate_kernel(const __half* __restrict__ xn, const float* __restrict__ gw,
                            const float* __restrict__ gb, float* __restrict__ out)
{
    int row  = blockIdx.x * 8 + (threadIdx.x >> 5);
    int lane = threadIdx.x & 31;
    if (row >= BLTOT) return;
    const __half* xr = xn + (size_t)row * CDIM;
    float acc[12];
#pragma unroll
    for (int h = 0; h < 12; h++) acc[h] = 0.f;
    for (int c = lane; c < CDIM; c += 32) {
        float xv = __half2float(xr[c]);
        const float* g = gw + c * 12;
#pragma unroll
        for (int h = 0; h < 12; h++) acc[h] += xv * g[h];
    }
#pragma unroll
    for (int h = 0; h < 12; h++)
#pragma unroll
        for (int o = 16; o; o >>= 1) acc[h] += __shfl_xor_sync(0xffffffffu, acc[h], o);
    if (lane == 0) {
#pragma unroll
        for (int h = 0; h < 12; h++) {
            float a = acc[h] + gb[h];
            out[(size_t)row * NHA + h] = 1.f / (1.f + expf(-a));
        }
    }
}

// ---------------- window attention (fp16 qkv) -> gated fp16 into cat[:, 768:1152] ----------------
__global__ void __launch_bounds__(64)
attn_kernel(const __half* __restrict__ qkv, const float* __restrict__ gate,
            __half* __restrict__ oh)
{
    int wid = blockIdx.x;
    int h   = blockIdx.y;
    int b   = wid >> 6;
    int rem = wid & 63;
    int wh  = rem >> 3;
    int ww  = rem & 7;
    __shared__ float q[49][33], k[49][33], v[49][33];
    int tid = threadIdx.x;
    for (int idx = tid; idx < 49 * 32; idx += 64) {
        int i = idx >> 5, d = idx & 31;
        int r = i / 7, c = i % 7;
        int l = (wh * 7 + r) * WW + ww * 7 + c;
        size_t rowoff = ((size_t)b * LSEQ + l) * 1152 + h * 32 + d;
        q[i][d] = __half2float(qkv[rowoff]) * 0.17677669529663687f;
        k[i][d] = __half2float(qkv[rowoff + 384]);
        v[i][d] = __half2float(qkv[rowoff + 768]);
    }
    __syncthreads();
    if (tid < 49) {
        int i = tid;
        int r = i / 7, c = i % 7;
        int l = (wh * 7 + r) * WW + ww * 7 + c;
        float sc[49];
        float mx = -1e30f;
        for (int j = 0; j < 49; j++) {
            float a = 0.f;
#pragma unroll
            for (int d = 0; d < 32; d++) a += q[i][d] * k[j][d];
            sc[j] = a;
            mx = fmaxf(mx, a);
        }
        float sum = 0.f;
        for (int j = 0; j < 49; j++) { sc[j] = expf(sc[j] - mx); sum += sc[j]; }
        float ga = gate[((size_t)b * LSEQ + l) * NHA + h];
        float inv = ga / sum;
        size_t o0 = ((size_t)b * LSEQ + l) * KCAT + DINNER + h * 32;
#pragma unroll
        for (int d = 0; d < 32; d++) {
            float o = 0.f;
            for (int j = 0; j < 49; j++) o += sc[j] * v[j][d];
            oh[o0 + d] = __float2half_rn(o * inv);
        }
    }
}

// ---------------- launch ----------------
static void* devptr(const void* sym) {
    void* p = nullptr;
    cudaGetSymbolAddress(&p, sym);
    return p;
}

extern "C" void kernel_launch(void* const* d_in, const int* in_sizes, int n_in,
                              void* d_out, int out_size)
{
    const float* x       = (const float*)d_in[0];
    const float* norm1_w = (const float*)d_in[1];
    const float* norm1_b = (const float*)d_in[2];
    const float* W_in    = (const float*)d_in[3];
    const float* conv_w  = (const float*)d_in[4];
    const float* conv_b  = (const float*)d_in[5];
    const float* dt_bias = (const float*)d_in[6];
    const float* A_log   = (const float*)d_in[7];
    const float* Dp      = (const float*)d_in[8];
    const float* mnorm_w = (const float*)d_in[9];
    const float* W_out   = (const float*)d_in[10];
    const float* qkv_w   = (const float*)d_in[11];
    const float* qkv_b   = (const float*)d_in[12];
    const float* gate_w  = (const float*)d_in[13];
    const float* gate_b  = (const float*)d_in[14];
    const float* proj_w  = (const float*)d_in[15];
    const float* proj_b  = (const float*)d_in[16];
    const float* fusion_w= (const float*)d_in[17];
    const float* fusion_b= (const float*)d_in[18];
    const float* norm2_w = (const float*)d_in[19];
    const float* norm2_b = (const float*)d_in[20];
    const float* fc1_w   = (const float*)d_in[21];
    const float* fc1_b   = (const float*)d_in[22];
    const float* fc2_w   = (const float*)d_in[23];
    const float* fc2_b   = (const float*)d_in[24];
    float* out = (float*)d_out;

    cudaFuncSetAttribute(mma_gemm, cudaFuncAttributeMaxDynamicSharedMemorySize, GEMM_SMEM);

    float* p_xs  = (float*)devptr(g_xs);
    float* p_Bm  = (float*)devptr(g_Bm);
    float* p_Cm  = (float*)devptr(g_Cm);
    float* p_dt  = (float*)devptr(g_dt);
    float* p_dA  = (float*)devptr(g_dA);
    float* p_y   = (float*)devptr(g_y);
    float* p_gt  = (float*)devptr(g_gate);
    float* p_x2  = (float*)devptr(g_x2);
    float* p_bF  = (float*)devptr(g_biasF);

    __half* zx_h  = (__half*)devptr(b_zx);
    __half* xn_h  = (__half*)devptr(b_xn);
    __half* cat_h = (__half*)devptr(b_cat);
    __half* h1_h  = (__half*)devptr(b_h1);
    __half* xn2_h = (__half*)devptr(b_xn2);
    __half* qkv_h = (__half*)devptr(b_qkv);

    __half* pw_in   = (__half*)devptr(w_in);
    __half* pw_qkv  = (__half*)devptr(w_qkv);
    __half* pw_fc1  = (__half*)devptr(w_fc1);
    __half* pw_fc2  = (__half*)devptr(w_fc2);
    __half* pw_fusA = (__half*)devptr(w_fusA);
    __half* pw_fusB = (__half*)devptr(w_fusB);
    __half* pw_outD = (__half*)devptr(w_outD);
    __half* pw_prjD = (__half*)devptr(w_prjD);
    __half* pw_catF = (__half*)devptr(w_catF);

    // 1) batched weight transpose/copy + fp16 (ONE kernel, 8 jobs)
    {
        WJob j0{W_in,                 pw_in,   CDIM,            DINPROJ, 0};  // transpose
        WJob j1{qkv_w,                pw_qkv,  CDIM,            1152,    0};  // transpose
        WJob j2{fc1_w,                pw_fc1,  CDIM,            1536,    0};  // transpose
        WJob j3{fc2_w,                pw_fc2,  1536,            CDIM,    0};  // transpose
        WJob j4{fusion_w,             pw_fusA, CDIM,            CDIM,    0};  // F1^T
        WJob j5{fusion_w + CDIM*CDIM, pw_fusB, CDIM,            CDIM,    0};  // F2^T
        WJob j6{W_out,                pw_outD, DINNER * CDIM,   1,       0};  // direct copy
        WJob j7{proj_w,               pw_prjD, CDIM * CDIM,     1,       0};  // direct copy
        long off = 0;
        j0.off = off; off += (long)j0.K * j0.N;
        j1.off = off; off += (long)j1.K * j1.N;
        j2.off = off; off += (long)j2.K * j2.N;
        j3.off = off; off += (long)j3.K * j3.N;
        j4.off = off; off += (long)j4.K * j4.N;
        j5.off = off; off += (long)j5.K * j5.N;
        j6.off = off; off += (long)j6.K * j6.N;
        j7.off = off; off += (long)j7.K * j7.N;
        wconv_all_kernel<<<(unsigned)((off + 255) / 256), 256>>>(j0, j1, j2, j3, j4, j5, j6, j7, off);
    }

    // 2) combined bias + weight folds into w_catF (offset trick via ldh)
    biasf_kernel<<<48, 256>>>(fusion_b, proj_b, fusion_w, p_bF);
    //    w_catF[n][0:768]   = folded W_out@F1
    mma_gemm<<<dim3(6, 3), 256, GEMM_SMEM>>>(pw_fusA, pw_outD,
        nullptr, nullptr, nullptr, pw_catF, KCAT, CDIM, DINNER, CDIM, 0);
    //    w_catF[n][768:1152] = folded proj@F2
    mma_gemm<<<dim3(3, 3), 256, GEMM_SMEM>>>(pw_fusB, pw_prjD,
        nullptr, nullptr, nullptr, pw_catF + DINNER, KCAT, CDIM, CDIM, CDIM, 0);

    // 3) norm1 -> fp16
    ln_kernel<<<BLTOT / 8, 256>>>(x, norm1_w, norm1_b, xn_h);

    // 4) attention gate
    gate_kernel<<<BLTOT / 8, 256>>>(xn_h, gate_w, gate_b, p_gt);

    // 5) qkv -> fp16 (bias fused)
    mma_gemm<<<dim3(9, MTILES), 256, GEMM_SMEM>>>(xn_h, pw_qkv,
        qkv_b, nullptr, nullptr, qkv_h, 1152, BLTOT, 1152, CDIM, 0);

    // 6) window attention -> cat[:, 768:1152]
    attn_kernel<<<dim3(NWIN, NHA), 64>>>(qkv_h, p_gt, cat_h);

    // 7) in_proj -> zx (fp16)
    mma_gemm<<<dim3(14, MTILES), 256, GEMM_SMEM>>>(xn_h, pw_in,
        nullptr, nullptr, nullptr, zx_h, DINPROJ, BLTOT, DINPROJ, CDIM, 0);

    // 8) conv + 9) dt
    {
        long tot = (long)BLTOT * CONVDIM;
        conv_kernel<<<(unsigned)((tot + 255) / 256), 256>>>(zx_h, conv_w, conv_b, p_xs, p_Bm, p_Cm);
        long tot2 = (long)BLTOT * NHM;
        dt_kernel<<<(unsigned)((tot2 + 255) / 256), 256>>>(zx_h, dt_bias, A_log, p_dt, p_dA);
    }

    // 10) scan
    scan_kernel<<<NB * NHM, 512>>>(p_xs, p_Bm, p_Cm, p_dt, p_dA, Dp, p_y);

    // 11) gated rmsnorm -> cat[:, 0:768]
    rmsgate_kernel<<<BLTOT / 8, 256>>>(p_y, zx_h, mnorm_w, cat_h);

    // 12) MERGED tail: x2 = x + cat @ w_catF + biasF   (K=1152, one GEMM)
    mma_gemm<<<dim3(3, MTILES), 256, GEMM_SMEM>>>(cat_h, pw_catF,
        p_bF, x, p_x2, nullptr, 0, BLTOT, CDIM, KCAT, 0);

    // 13) norm2 -> xn2 fp16
    ln_kernel<<<BLTOT / 8, 256>>>(p_x2, norm2_w, norm2_b, xn2_h);

    // 14) MLP fc1 + 15) fc2
    mma_gemm<<<dim3(12, MTILES), 256, GEMM_SMEM>>>(xn2_h, pw_fc1,
        fc1_b, nullptr, nullptr, h1_h, 1536, BLTOT, 1536, CDIM, 1);
    mma_gemm<<<dim3(3, MTILES), 256, GEMM_SMEM>>>(h1_h, pw_fc2,
        fc2_b, p_x2, out, nullptr, 0, BLTOT, CDIM, 1536, 0);
}